// round 1
// baseline (speedup 1.0000x reference)
#include <cuda_runtime.h>
#include <cuda_bf16.h>

// Problem constants (fixed by the reference):
//   B=4096 scenes, L=200 padded tokens, V=50000 vocab, H=128 hidden.
// out[i,h] = b[h] + sum_{j < len_i} W[h, tokens[i,j]]
// Strategy: transpose W -> Wt[V,H] (contiguous 512B rows), then one warp per
// scene gathers+sums rows of Wt. W fits in L2 (25.6MB), so the gather is
// L2-bandwidth bound.

#define B_N 4096
#define L_N 200
#define V_N 50000
#define H_N 128

// Scratch: transposed weights, [V, H] row-major. 25.6 MB static device array
// (allocation-free per harness rules).
__device__ float g_Wt[(size_t)V_N * H_N];

// ---------------------------------------------------------------------------
// Tiled transpose: W[H,V] row-major -> g_Wt[V,H] row-major.
// Block (32,8), grid (ceil(V/32), H/32). Shared tile with +1 padding.
// ---------------------------------------------------------------------------
__global__ void __launch_bounds__(256) transpose_W_kernel(const float* __restrict__ W) {
    __shared__ float tile[32][33];
    int v0 = blockIdx.x * 32;
    int h0 = blockIdx.y * 32;
    int x = threadIdx.x;          // 0..31
    int y = threadIdx.y;          // 0..7

    // Read: rows of W (coalesced along v)
    #pragma unroll
    for (int i = 0; i < 32; i += 8) {
        int v = v0 + x;
        int h = h0 + y + i;
        if (v < V_N) tile[y + i][x] = W[(size_t)h * V_N + v];
    }
    __syncthreads();
    // Write: rows of Wt (coalesced along h)
    #pragma unroll
    for (int i = 0; i < 32; i += 8) {
        int v = v0 + y + i;
        int h = h0 + x;
        if (v < V_N) g_Wt[(size_t)v * H_N + h] = tile[x][y + i];
    }
}

// ---------------------------------------------------------------------------
// Gather-sum: one warp per scene. Lane owns 4 consecutive h via float4.
// Tokens loaded coalesced in chunks of 32, broadcast with shfl.
// ---------------------------------------------------------------------------
__global__ void __launch_bounds__(256) bow_gather_kernel(
    const int* __restrict__ tokens,
    const int* __restrict__ lengths,
    const float* __restrict__ bias,
    float* __restrict__ out)
{
    int gwarp = (int)((blockIdx.x * blockDim.x + threadIdx.x) >> 5);
    int lane  = threadIdx.x & 31;
    if (gwarp >= B_N) return;

    int len = lengths[gwarp];
    const int* tok = tokens + (size_t)gwarp * L_N;

    // acc starts at bias (lane -> h = 4*lane .. 4*lane+3)
    float4 acc = reinterpret_cast<const float4*>(bias)[lane];

    int nfull = len & ~31;
    for (int j0 = 0; j0 < nfull; j0 += 32) {
        int myTok = tok[j0 + lane];            // coalesced token chunk
        #pragma unroll 8
        for (int k = 0; k < 32; k++) {
            int t = __shfl_sync(0xffffffffu, myTok, k);
            float4 w = reinterpret_cast<const float4*>(g_Wt + (size_t)t * H_N)[lane];
            acc.x += w.x; acc.y += w.y; acc.z += w.z; acc.w += w.w;
        }
    }
    int rem = len - nfull;
    if (rem > 0) {
        int jj = nfull + lane;
        int myTok = tok[jj < L_N ? jj : (L_N - 1)];   // stay in-bounds; unused lanes ignored
        for (int k = 0; k < rem; k++) {
            int t = __shfl_sync(0xffffffffu, myTok, k);
            float4 w = reinterpret_cast<const float4*>(g_Wt + (size_t)t * H_N)[lane];
            acc.x += w.x; acc.y += w.y; acc.z += w.z; acc.w += w.w;
        }
    }

    reinterpret_cast<float4*>(out + (size_t)gwarp * H_N)[lane] = acc;
}

// ---------------------------------------------------------------------------
// kernel_launch: transpose then gather, same (default) stream, graph-capturable.
// Inputs (metadata order): tokens[int32, B*L], lengths[int32, B],
//                          W[f32, H*V], b[f32, H]. Output: f32 [B, H].
// ---------------------------------------------------------------------------
extern "C" void kernel_launch(void* const* d_in, const int* in_sizes, int n_in,
                              void* d_out, int out_size) {
    const int*   tokens  = (const int*)d_in[0];
    const int*   lengths = (const int*)d_in[1];
    const float* W       = (const float*)d_in[2];
    const float* bias    = (const float*)d_in[3];
    float*       out     = (float*)d_out;

    (void)in_sizes; (void)n_in; (void)out_size;

    dim3 tgrid((V_N + 31) / 32, H_N / 32);
    dim3 tblock(32, 8);
    transpose_W_kernel<<<tgrid, tblock>>>(W);

    // 4096 warps, 8 warps (256 threads) per block -> 512 blocks
    int threads = 256;
    int warpsPerBlock = threads / 32;
    int blocks = (B_N + warpsPerBlock - 1) / warpsPerBlock;
    bow_gather_kernel<<<blocks, threads>>>(tokens, lengths, bias, out);
}